// round 12
// baseline (speedup 1.0000x reference)
#include <cuda_runtime.h>
#include <math.h>

#define B_ 256
#define T_ 250
#define I_ 700
#define H_ 128
#define O_ 20

// Scratch: xin[b][t][h] = (x @ w_ih1 + b_ih1), 32.77 MB static device array
__device__ float g_xin[B_ * T_ * H_];

// ---------------------------------------------------------------------------
// Kernel 1: xin = x @ w_ih1 + b_ih1   (M=64000, K=700, N=128)
// EXACT-FP32 SGEMM, per-element fully-serial fmaf ascending k (bit-matches a
// classic serial-k SGEMM mainloop). Bias added once after the full sum.
// ---------------------------------------------------------------------------
__global__ __launch_bounds__(256) void gemm_xin_kernel(
    const float* __restrict__ x, const float* __restrict__ w,
    const float* __restrict__ bias)
{
    __shared__ float As[8][128];
    __shared__ float Bs[8][128];
    const int tid = threadIdx.x;
    const int m0  = blockIdx.x * 128;
    const int tr = tid >> 4, tc = tid & 15;            // 16x16 thread grid, 8x8 each
    const int arow = tid >> 1, acol = (tid & 1) * 4;   // A loads: 4 consecutive k
    const int brow = tid >> 5, bcol = (tid & 31) * 4;  // B loads: float4
    const float* xrow = x + (size_t)(m0 + arow) * I_;

    float c[8][8];
#pragma unroll
    for (int i = 0; i < 8; ++i)
#pragma unroll
        for (int j = 0; j < 8; ++j) c[i][j] = 0.f;

    for (int k0 = 0; k0 < I_; k0 += 8) {
#pragma unroll
        for (int i = 0; i < 4; ++i) {
            int k = k0 + acol + i;
            As[acol + i][arow] = (k < I_) ? xrow[k] : 0.f;   // exact fp32
        }
        {
            int kb = k0 + brow;
            float4 v = make_float4(0.f, 0.f, 0.f, 0.f);
            if (kb < I_) v = *reinterpret_cast<const float4*>(w + (size_t)kb * H_ + bcol);
            Bs[brow][bcol + 0] = v.x; Bs[brow][bcol + 1] = v.y;   // exact fp32
            Bs[brow][bcol + 2] = v.z; Bs[brow][bcol + 3] = v.w;
        }
        __syncthreads();
#pragma unroll
        for (int k = 0; k < 8; ++k) {
            float a[8], bb[8];
#pragma unroll
            for (int i = 0; i < 8; ++i) a[i] = As[k][tr * 8 + i];
#pragma unroll
            for (int j = 0; j < 8; ++j) bb[j] = Bs[k][tc * 8 + j];
#pragma unroll
            for (int i = 0; i < 8; ++i)
#pragma unroll
                for (int j = 0; j < 8; ++j) c[i][j] = fmaf(a[i], bb[j], c[i][j]);
        }
        __syncthreads();
    }
#pragma unroll
    for (int i = 0; i < 8; ++i) {
        int m = m0 + tr * 8 + i;
        float* orow = g_xin + (size_t)m * H_;
#pragma unroll
        for (int j = 0; j < 8; j += 4) {
            int n = tc * 8 + j;
            float4 v;
            v.x = __fadd_rn(c[i][j + 0], bias[n + 0]);
            v.y = __fadd_rn(c[i][j + 1], bias[n + 1]);
            v.z = __fadd_rn(c[i][j + 2], bias[n + 2]);
            v.w = __fadd_rn(c[i][j + 3], bias[n + 3]);
            *reinterpret_cast<float4*>(orow + n) = v;
        }
    }
}

// ---------------------------------------------------------------------------
// Kernel 2: the sequential scan. 128 blocks x 256 threads; 2 batch rows per
// block (thread = one hidden unit of one row). ALL weights EXACT fp32 in SMEM
// (all-exact gave the best out0; out1 theory: elementwise FMA-contraction /
// exp mismatch, not matmul precision). Masked matvecs are serial ascending-k
// RN adds — bit-identical to a serial-k SGEMM with a binary input vector.
// Dynamics in separate RN intrinsics (XLA emits separate mul/add, never
// contracts). Decay constants: f32 RN division for the argument, then
// correctly-rounded exp via double.
// ---------------------------------------------------------------------------
#define SCAN_SMEM_FLOATS (3 * H_ * H_ + H_ * O_ + 3 * H_ + O_)
#define SCAN_SMEM_BYTES  (SCAN_SMEM_FLOATS * 4 + 32 * 4)

// masked matvec, serial ascending-k RN adds from zero
__device__ __forceinline__ float masked_mv(const unsigned* mp, const float* base, int h)
{
    float acc = 0.f;
#pragma unroll
    for (int w = 0; w < 4; ++w) {
        unsigned bits = mp[w];
        const float* col = base + (w * 32) * H_ + h;
        while (bits) { int j = __ffs(bits) - 1; bits &= bits - 1;
                       acc = __fadd_rn(acc, col[j * H_]); }
    }
    return acc;
}

__global__ __launch_bounds__(256, 1) void scan_kernel(
    const float* __restrict__ mask,
    const float* __restrict__ w_h1h1, const float* __restrict__ b_h1h1,
    const float* __restrict__ w_h1h2, const float* __restrict__ b_h1h2,
    const float* __restrict__ w_h2h2, const float* __restrict__ b_h2h2,
    const float* __restrict__ w_h2o,  const float* __restrict__ b_h2o,
    const float* __restrict__ tau_adp_h1, const float* __restrict__ tau_adp_h2,
    const float* __restrict__ tau_m_h1,   const float* __restrict__ tau_m_h2,
    const float* __restrict__ tau_m_o,
    const float* __restrict__ hid1_mem0,  const float* __restrict__ hid2_mem0,
    const float* __restrict__ out_mem0,
    float* __restrict__ out)
{
    extern __shared__ float sm[];
    float* sw11 = sm;                    // 128x128 (mask-applied, exact fp32)
    float* sw12 = sw11 + H_ * H_;        // 128x128 (exact fp32)
    float* sw22 = sw12 + H_ * H_;        // 128x128 (mask-applied, exact fp32)
    float* sw2o = sw22 + H_ * H_;        // 128x20  (exact fp32)
    float* sb1  = sw2o + H_ * O_;        // 128
    float* sb12 = sb1 + H_;              // 128
    float* sb22 = sb12 + H_;             // 128
    float* sbo  = sb22 + H_;             // 20
    unsigned* mk = (unsigned*)(sbo + O_); // spike masks: m1[2][2][4], m2[2][2][4]

    const int tid  = threadIdx.x;
    const int row  = tid >> 7;       // 0..1  (batch row within block)
    const int h    = tid & 127;      // hidden unit
    const int lane = tid & 31;
    const int wir  = (tid >> 5) & 3; // warp index within row
    const int b    = blockIdx.x * 2 + row;

    for (int i = tid; i < H_ * H_; i += 256) {
        sw11[i] = __fmul_rn(w_h1h1[i], mask[i]);            // exact fp32
        sw12[i] = w_h1h2[i];                                // exact fp32
        sw22[i] = __fmul_rn(w_h2h2[i], mask[H_ * H_ + i]);  // exact fp32
    }
    for (int i = tid; i < H_ * O_; i += 256) sw2o[i] = w_h2o[i];  // exact fp32
    if (tid < H_) { sb1[tid] = b_h1h1[tid]; sb12[tid] = b_h1h2[tid]; sb22[tid] = b_h2h2[tid]; }
    if (tid < O_) sbo[tid] = b_h2o[tid];
    if (tid < 32) mk[tid] = 0u;

    // decay constants: f32 RN division (XLA computes -DT/tau in f32), then
    // exp evaluated in double and rounded once -> correctly-rounded f32 exp
    const float a1 = (float)exp((double)__fdiv_rn(-1.f, tau_m_h1[h]));
    const float r1 = (float)exp((double)__fdiv_rn(-1.f, tau_adp_h1[h]));
    const float a2 = (float)exp((double)__fdiv_rn(-1.f, tau_m_h2[h]));
    const float r2 = (float)exp((double)__fdiv_rn(-1.f, tau_adp_h2[h]));

    float h1m = hid1_mem0[b * H_ + h];
    float h2m = hid2_mem0[b * H_ + h];
    float b1 = 0.01f, b2 = 0.01f;       // adaptation baselines (B_J0)
    float s1p = 0.f, s2p = 0.f;         // previous spikes (this unit)
    float s1c = 0.f, s2c = 0.f;         // spike counters

    float ao = 1.f, om = 0.f, accO = 0.f;
    if (wir == 0 && lane < O_) {
        ao = (float)exp((double)__fdiv_rn(-1.f, tau_m_o[lane]));
        om = out_mem0[b * O_ + lane];
    }
    __syncthreads();

    unsigned* m1 = mk;       // [phase][row][word]
    unsigned* m2 = mk + 16;

    float xnext = g_xin[(b * T_) * H_ + h];   // prefetch t=0

    for (int t = 0; t < T_; ++t) {
        const int cur = t & 1, prv = cur ^ 1;
        float xv = xnext;
        if (t + 1 < T_) xnext = g_xin[(b * T_ + t + 1) * H_ + h];

        // ---- layer 1 (adaptive LIF) ----
        float acc = masked_mv(m1 + (prv * 2 + row) * 4, sw11, h);
        float i1 = __fadd_rn(__fadd_rn(xv, acc), sb1[h]);   // (xt + dot) + bias
        b1 = __fadd_rn(__fmul_rn(r1, b1), __fmul_rn(__fsub_rn(1.f, r1), s1p));
        float B1 = __fadd_rn(0.01f, __fmul_rn(1.8f, b1));
        h1m = __fsub_rn(__fadd_rn(__fmul_rn(h1m, a1),
                                  __fmul_rn(__fsub_rn(1.f, a1), i1)),
                        __fmul_rn(B1, s1p));
        float ns1 = __fsub_rn(h1m, B1) > 0.f ? 1.f : 0.f;
        s1c += ns1;
        unsigned bal1 = __ballot_sync(0xffffffffu, ns1 != 0.f);
        if (lane == 0) m1[(cur * 2 + row) * 4 + wir] = bal1;
        s1p = ns1;
        __syncthreads();

        // ---- layer 2 (adaptive LIF) ----
        float acc12 = masked_mv(m1 + (cur * 2 + row) * 4, sw12, h);
        float acc22 = masked_mv(m2 + (prv * 2 + row) * 4, sw22, h);
        // ((dot12 + b12) + dot22) + b22 (reference association)
        float i2 = __fadd_rn(__fadd_rn(__fadd_rn(acc12, sb12[h]), acc22), sb22[h]);
        b2 = __fadd_rn(__fmul_rn(r2, b2), __fmul_rn(__fsub_rn(1.f, r2), s2p));
        float B2 = __fadd_rn(0.01f, __fmul_rn(1.8f, b2));
        h2m = __fsub_rn(__fadd_rn(__fmul_rn(h2m, a2),
                                  __fmul_rn(__fsub_rn(1.f, a2), i2)),
                        __fmul_rn(B2, s2p));
        float ns2 = __fsub_rn(h2m, B2) > 0.f ? 1.f : 0.f;
        s2c += ns2;
        unsigned bal2 = __ballot_sync(0xffffffffu, ns2 != 0.f);
        if (lane == 0) m2[(cur * 2 + row) * 4 + wir] = bal2;
        s2p = ns2;
        __syncthreads();

        // ---- leaky-integrator readout + running softmax (warp 0 of each row) ----
        if (wir == 0) {
            const unsigned* mpc = m2 + (cur * 2 + row) * 4;
            if (lane < O_) {
                // dot accumulated from ZERO, bias added after (ref: dot + b)
                float dot = 0.f;
#pragma unroll
                for (int w = 0; w < 4; ++w) {
                    unsigned bits = mpc[w];
                    const float* col = sw2o + (w * 32) * O_ + lane;
                    while (bits) { int j = __ffs(bits) - 1; bits &= bits - 1;
                                   dot = __fadd_rn(dot, col[j * O_]); }
                }
                float io = __fadd_rn(dot, sbo[lane]);
                om = __fadd_rn(__fmul_rn(ao, om),
                               __fmul_rn(__fsub_rn(1.f, ao), io));
            }
            // softmax: max (order-insensitive), then exp, then SERIAL
            // ascending-index sum (matches XLA's per-row serial reduce)
            float v = (lane < O_) ? om : -3.402823466e38f;
#pragma unroll
            for (int off = 16; off; off >>= 1)
                v = fmaxf(v, __shfl_xor_sync(0xffffffffu, v, off));
            float e = (lane < O_) ? expf(__fsub_rn(om, v)) : 0.f;
            float s = 0.f;
#pragma unroll
            for (int j = 0; j < O_; ++j)
                s = __fadd_rn(s, __shfl_sync(0xffffffffu, e, j));
            if (t > 10 && lane < O_) accO = __fadd_rn(accO, __fdiv_rn(e, s));
        }
    }

    // outputs: [acc (B,O)] [s1/T (B,H)] [s2/T (B,H)] [A_norm]
    if (wir == 0 && lane < O_) out[b * O_ + lane] = accO;
    out[B_ * O_ + b * H_ + h]            = __fdiv_rn(s1c, (float)T_);
    out[B_ * O_ + B_ * H_ + b * H_ + h]  = __fdiv_rn(s2c, (float)T_);
}

// ---------------------------------------------------------------------------
// Kernel 3: A_norm = sum|w_h1h1*mask0| + sum|w_h2h2*mask1|  (fp32)
// ---------------------------------------------------------------------------
__global__ void anorm_kernel(const float* __restrict__ w11, const float* __restrict__ w22,
                             const float* __restrict__ mask, float* __restrict__ out)
{
    __shared__ float red[256];
    float s = 0.f;
    for (int i = threadIdx.x; i < H_ * H_; i += 256)
        s = __fadd_rn(s, __fadd_rn(fabsf(__fmul_rn(w11[i], mask[i])),
                                   fabsf(__fmul_rn(w22[i], mask[H_ * H_ + i]))));
    red[threadIdx.x] = s;
    __syncthreads();
    for (int o = 128; o > 0; o >>= 1) {
        if (threadIdx.x < o) red[threadIdx.x] = __fadd_rn(red[threadIdx.x], red[threadIdx.x + o]);
        __syncthreads();
    }
    if (threadIdx.x == 0) out[B_ * O_ + 2 * B_ * H_] = red[0];
}

// ---------------------------------------------------------------------------
extern "C" void kernel_launch(void* const* d_in, const int* in_sizes, int n_in,
                              void* d_out, int out_size)
{
    const float* x          = (const float*)d_in[0];
    const float* mask       = (const float*)d_in[1];
    const float* w_ih1      = (const float*)d_in[2];
    const float* b_ih1      = (const float*)d_in[3];
    const float* w_h1h1     = (const float*)d_in[4];
    const float* b_h1h1     = (const float*)d_in[5];
    const float* w_h1h2     = (const float*)d_in[6];
    const float* b_h1h2     = (const float*)d_in[7];
    const float* w_h2h2     = (const float*)d_in[8];
    const float* b_h2h2     = (const float*)d_in[9];
    const float* w_h2o      = (const float*)d_in[10];
    const float* b_h2o      = (const float*)d_in[11];
    const float* tau_adp_h1 = (const float*)d_in[12];
    const float* tau_adp_h2 = (const float*)d_in[13];
    const float* tau_m_h1   = (const float*)d_in[14];
    const float* tau_m_h2   = (const float*)d_in[15];
    const float* tau_m_o    = (const float*)d_in[16];
    const float* hid1_mem0  = (const float*)d_in[17];
    const float* hid2_mem0  = (const float*)d_in[18];
    const float* out_mem0   = (const float*)d_in[19];
    float* out = (float*)d_out;

    // opt-in to >48KB dynamic smem for the scan kernel (host-side attribute,
    // not a stream op; graph-capture safe)
    cudaFuncSetAttribute(scan_kernel, cudaFuncAttributeMaxDynamicSharedMemorySize,
                         SCAN_SMEM_BYTES);

    gemm_xin_kernel<<<(B_ * T_) / 128, 256>>>(x, w_ih1, b_ih1);
    scan_kernel<<<B_ / 2, 256, SCAN_SMEM_BYTES>>>(
        mask, w_h1h1, b_h1h1, w_h1h2, b_h1h2, w_h2h2, b_h2h2, w_h2o, b_h2o,
        tau_adp_h1, tau_adp_h2, tau_m_h1, tau_m_h2, tau_m_o,
        hid1_mem0, hid2_mem0, out_mem0, out);
    anorm_kernel<<<1, 256>>>(w_h1h1, w_h2h2, mask, out);
}

// round 14
// speedup vs baseline: 1.0217x; 1.0217x over previous
#include <cuda_runtime.h>
#include <math.h>

#define B_ 256
#define T_ 250
#define I_ 700
#define H_ 128
#define O_ 20

// Scratch: xin[b][t][h] = (x @ w_ih1 + b_ih1), 32.77 MB static device array
__device__ float g_xin[B_ * T_ * H_];

// ---------------------------------------------------------------------------
// Kernel 1: xin = x @ w_ih1 + b_ih1   (M=64000, K=700, N=128)
// EXACT-FP32 SGEMM, per-element fully-serial fmaf ascending k (bit-identical
// to R12). Double-buffered SMEM pipeline: prefetch next k-tile into registers
// during compute, one __syncthreads per tile.
// ---------------------------------------------------------------------------
__global__ __launch_bounds__(256) void gemm_xin_kernel(
    const float* __restrict__ x, const float* __restrict__ w,
    const float* __restrict__ bias)
{
    __shared__ float As[2][8][128];
    __shared__ float Bs[2][8][128];
    const int tid = threadIdx.x;
    const int m0  = blockIdx.x * 128;
    const int tr = tid >> 4, tc = tid & 15;            // 16x16 thread grid, 8x8 each
    const int arow = tid >> 1, acol = (tid & 1) * 4;   // A loads: 4 consecutive k
    const int brow = tid >> 5, bcol = (tid & 31) * 4;  // B loads: float4
    const float* xrow = x + (size_t)(m0 + arow) * I_;
    const int NT = (I_ + 7) / 8;                       // 88 k-tiles

    float c[8][8];
#pragma unroll
    for (int i = 0; i < 8; ++i)
#pragma unroll
        for (int j = 0; j < 8; ++j) c[i][j] = 0.f;

    // preload tile 0 into buffer 0
#pragma unroll
    for (int i = 0; i < 4; ++i) {
        int k = acol + i;
        As[0][acol + i][arow] = (k < I_) ? xrow[k] : 0.f;
    }
    {
        int kb = brow;
        float4 v = make_float4(0.f, 0.f, 0.f, 0.f);
        if (kb < I_) v = *reinterpret_cast<const float4*>(w + (size_t)kb * H_ + bcol);
        Bs[0][brow][bcol + 0] = v.x; Bs[0][brow][bcol + 1] = v.y;
        Bs[0][brow][bcol + 2] = v.z; Bs[0][brow][bcol + 3] = v.w;
    }
    __syncthreads();

    for (int kt = 0; kt < NT; ++kt) {
        const int cur = kt & 1, nxt = cur ^ 1;
        // prefetch next tile into registers (overlaps with compute below)
        float pa[4];
        float4 pb = make_float4(0.f, 0.f, 0.f, 0.f);
        if (kt + 1 < NT) {
#pragma unroll
            for (int i = 0; i < 4; ++i) {
                int k = (kt + 1) * 8 + acol + i;
                pa[i] = (k < I_) ? xrow[k] : 0.f;
            }
            int kb = (kt + 1) * 8 + brow;
            if (kb < I_) pb = *reinterpret_cast<const float4*>(w + (size_t)kb * H_ + bcol);
        }
        // compute current tile: serial ascending k per output (bit-exact)
#pragma unroll
        for (int k = 0; k < 8; ++k) {
            float4 a0 = *reinterpret_cast<const float4*>(&As[cur][k][tr * 8]);
            float4 a1 = *reinterpret_cast<const float4*>(&As[cur][k][tr * 8 + 4]);
            float4 b0 = *reinterpret_cast<const float4*>(&Bs[cur][k][tc * 8]);
            float4 b1 = *reinterpret_cast<const float4*>(&Bs[cur][k][tc * 8 + 4]);
            float a[8] = {a0.x, a0.y, a0.z, a0.w, a1.x, a1.y, a1.z, a1.w};
            float bb[8] = {b0.x, b0.y, b0.z, b0.w, b1.x, b1.y, b1.z, b1.w};
#pragma unroll
            for (int i = 0; i < 8; ++i)
#pragma unroll
                for (int j = 0; j < 8; ++j) c[i][j] = fmaf(a[i], bb[j], c[i][j]);
        }
        // store prefetched tile into the other buffer
        if (kt + 1 < NT) {
#pragma unroll
            for (int i = 0; i < 4; ++i) As[nxt][acol + i][arow] = pa[i];
            Bs[nxt][brow][bcol + 0] = pb.x; Bs[nxt][brow][bcol + 1] = pb.y;
            Bs[nxt][brow][bcol + 2] = pb.z; Bs[nxt][brow][bcol + 3] = pb.w;
        }
        __syncthreads();
    }
#pragma unroll
    for (int i = 0; i < 8; ++i) {
        int m = m0 + tr * 8 + i;
        float* orow = g_xin + (size_t)m * H_;
#pragma unroll
        for (int j = 0; j < 8; j += 4) {
            int n = tc * 8 + j;
            float4 v;
            v.x = __fadd_rn(c[i][j + 0], bias[n + 0]);
            v.y = __fadd_rn(c[i][j + 1], bias[n + 1]);
            v.z = __fadd_rn(c[i][j + 2], bias[n + 2]);
            v.w = __fadd_rn(c[i][j + 3], bias[n + 3]);
            *reinterpret_cast<float4*>(orow + n) = v;
        }
    }
}

// ---------------------------------------------------------------------------
// Kernel 2: the sequential scan — WARP-PER-ROW restructure (R13).
// 64 blocks x 128 threads; each warp owns one batch row, 4 hidden units per
// lane (h = g*32+lane). Spike masks are in-warp ballot results kept in
// registers (same bit layout: word g bit j <-> unit g*32+j), so the entire
// 250-step loop has ZERO __syncthreads and no SMEM mask traffic. All
// arithmetic ops/orders are bit-identical to the R12 passing kernel.
// ---------------------------------------------------------------------------
#define SCAN_SMEM_FLOATS (3 * H_ * H_ + H_ * O_)
#define SCAN_SMEM_BYTES  (SCAN_SMEM_FLOATS * 4)

__global__ __launch_bounds__(128, 1) void scan_kernel(
    const float* __restrict__ mask,
    const float* __restrict__ w_h1h1, const float* __restrict__ b_h1h1,
    const float* __restrict__ w_h1h2, const float* __restrict__ b_h1h2,
    const float* __restrict__ w_h2h2, const float* __restrict__ b_h2h2,
    const float* __restrict__ w_h2o,  const float* __restrict__ b_h2o,
    const float* __restrict__ tau_adp_h1, const float* __restrict__ tau_adp_h2,
    const float* __restrict__ tau_m_h1,   const float* __restrict__ tau_m_h2,
    const float* __restrict__ tau_m_o,
    const float* __restrict__ hid1_mem0,  const float* __restrict__ hid2_mem0,
    const float* __restrict__ out_mem0,
    float* __restrict__ out)
{
    extern __shared__ float sm[];
    float* sw11 = sm;                    // 128x128 (mask-applied, exact fp32)
    float* sw12 = sw11 + H_ * H_;        // 128x128 (exact fp32)
    float* sw22 = sw12 + H_ * H_;        // 128x128 (mask-applied, exact fp32)
    float* sw2o = sw22 + H_ * H_;        // 128x20  (exact fp32)

    const int tid  = threadIdx.x;
    const int wid  = tid >> 5;       // warp in block = row index within block
    const int lane = tid & 31;
    const int b    = blockIdx.x * 4 + wid;

    for (int i = tid; i < H_ * H_; i += 128) {
        sw11[i] = __fmul_rn(w_h1h1[i], mask[i]);
        sw12[i] = w_h1h2[i];
        sw22[i] = __fmul_rn(w_h2h2[i], mask[H_ * H_ + i]);
    }
    for (int i = tid; i < H_ * O_; i += 128) sw2o[i] = w_h2o[i];
    __syncthreads();   // the ONLY block-wide sync (weights ready)

    // per-unit constants/state, 4 units per lane: h = g*32 + lane
    float a1[4], r1[4], a2[4], r2[4], c1[4], c12[4], c22[4];
    float h1m[4], h2m[4], ab1[4], ab2[4], s1p[4], s2p[4], s1c[4], s2c[4];
#pragma unroll
    for (int g = 0; g < 4; ++g) {
        int h = g * 32 + lane;
        a1[g] = (float)exp((double)__fdiv_rn(-1.f, tau_m_h1[h]));
        r1[g] = (float)exp((double)__fdiv_rn(-1.f, tau_adp_h1[h]));
        a2[g] = (float)exp((double)__fdiv_rn(-1.f, tau_m_h2[h]));
        r2[g] = (float)exp((double)__fdiv_rn(-1.f, tau_adp_h2[h]));
        c1[g]  = b_h1h1[h];
        c12[g] = b_h1h2[h];
        c22[g] = b_h2h2[h];
        h1m[g] = hid1_mem0[b * H_ + h];
        h2m[g] = hid2_mem0[b * H_ + h];
        ab1[g] = 0.01f; ab2[g] = 0.01f;
        s1p[g] = 0.f; s2p[g] = 0.f; s1c[g] = 0.f; s2c[g] = 0.f;
    }
    const int lo = (lane < O_) ? lane : (O_ - 1);   // clamped readout column
    float ao = 1.f, om = 0.f, accO = 0.f, bo = 0.f;
    if (lane < O_) {
        ao = (float)exp((double)__fdiv_rn(-1.f, tau_m_o[lane]));
        om = out_mem0[b * O_ + lane];
        bo = b_h2o[lane];
    }

    unsigned m1w[4] = {0u, 0u, 0u, 0u};   // h1 spike masks (registers)
    unsigned m2w[4] = {0u, 0u, 0u, 0u};   // h2 spike masks (registers)

    float xv[4], xn[4];
#pragma unroll
    for (int g = 0; g < 4; ++g) xn[g] = g_xin[(size_t)(b * T_) * H_ + g * 32 + lane];

    for (int t = 0; t < T_; ++t) {
#pragma unroll
        for (int g = 0; g < 4; ++g) xv[g] = xn[g];
        if (t + 1 < T_) {
#pragma unroll
            for (int g = 0; g < 4; ++g)
                xn[g] = g_xin[(size_t)(b * T_ + t + 1) * H_ + g * 32 + lane];
        }

        // ---- layer 1 (adaptive LIF) ----
        float acc[4] = {0.f, 0.f, 0.f, 0.f};
#pragma unroll
        for (int w = 0; w < 4; ++w) {
            unsigned bits = m1w[w];
            const float* rb = sw11 + (w * 32) * H_ + lane;
            while (bits) {
                int j = __ffs(bits) - 1; bits &= bits - 1;
                const float* r = rb + j * H_;
#pragma unroll
                for (int g = 0; g < 4; ++g) acc[g] = __fadd_rn(acc[g], r[g * 32]);
            }
        }
        float ns1[4];
#pragma unroll
        for (int g = 0; g < 4; ++g) {
            float i1 = __fadd_rn(__fadd_rn(xv[g], acc[g]), c1[g]);
            ab1[g] = __fadd_rn(__fmul_rn(r1[g], ab1[g]),
                               __fmul_rn(__fsub_rn(1.f, r1[g]), s1p[g]));
            float B1 = __fadd_rn(0.01f, __fmul_rn(1.8f, ab1[g]));
            h1m[g] = __fsub_rn(__fadd_rn(__fmul_rn(h1m[g], a1[g]),
                                         __fmul_rn(__fsub_rn(1.f, a1[g]), i1)),
                               __fmul_rn(B1, s1p[g]));
            ns1[g] = __fsub_rn(h1m[g], B1) > 0.f ? 1.f : 0.f;
            s1c[g] += ns1[g];
            s1p[g] = ns1[g];
        }
#pragma unroll
        for (int g = 0; g < 4; ++g)
            m1w[g] = __ballot_sync(0xffffffffu, ns1[g] != 0.f);

        // ---- layer 2 (adaptive LIF) ----
        float a12[4] = {0.f, 0.f, 0.f, 0.f}, a22[4] = {0.f, 0.f, 0.f, 0.f};
#pragma unroll
        for (int w = 0; w < 4; ++w) {
            unsigned bits = m1w[w];
            const float* rb = sw12 + (w * 32) * H_ + lane;
            while (bits) {
                int j = __ffs(bits) - 1; bits &= bits - 1;
                const float* r = rb + j * H_;
#pragma unroll
                for (int g = 0; g < 4; ++g) a12[g] = __fadd_rn(a12[g], r[g * 32]);
            }
        }
#pragma unroll
        for (int w = 0; w < 4; ++w) {
            unsigned bits = m2w[w];
            const float* rb = sw22 + (w * 32) * H_ + lane;
            while (bits) {
                int j = __ffs(bits) - 1; bits &= bits - 1;
                const float* r = rb + j * H_;
#pragma unroll
                for (int g = 0; g < 4; ++g) a22[g] = __fadd_rn(a22[g], r[g * 32]);
            }
        }
        float ns2[4];
#pragma unroll
        for (int g = 0; g < 4; ++g) {
            float i2 = __fadd_rn(__fadd_rn(__fadd_rn(a12[g], c12[g]), a22[g]), c22[g]);
            ab2[g] = __fadd_rn(__fmul_rn(r2[g], ab2[g]),
                               __fmul_rn(__fsub_rn(1.f, r2[g]), s2p[g]));
            float B2 = __fadd_rn(0.01f, __fmul_rn(1.8f, ab2[g]));
            h2m[g] = __fsub_rn(__fadd_rn(__fmul_rn(h2m[g], a2[g]),
                                         __fmul_rn(__fsub_rn(1.f, a2[g]), i2)),
                               __fmul_rn(B2, s2p[g]));
            ns2[g] = __fsub_rn(h2m[g], B2) > 0.f ? 1.f : 0.f;
            s2c[g] += ns2[g];
            s2p[g] = ns2[g];
        }
#pragma unroll
        for (int g = 0; g < 4; ++g)
            m2w[g] = __ballot_sync(0xffffffffu, ns2[g] != 0.f);

        // ---- leaky-integrator readout + running softmax (in-warp) ----
        {
            float dot = 0.f;
#pragma unroll
            for (int w = 0; w < 4; ++w) {
                unsigned bits = m2w[w];
                const float* rb = sw2o + (w * 32) * O_ + lo;
                while (bits) {
                    int j = __ffs(bits) - 1; bits &= bits - 1;
                    dot = __fadd_rn(dot, rb[j * O_]);
                }
            }
            if (lane < O_) {
                float io = __fadd_rn(dot, bo);
                om = __fadd_rn(__fmul_rn(ao, om),
                               __fmul_rn(__fsub_rn(1.f, ao), io));
            }
            float v = (lane < O_) ? om : -3.402823466e38f;
#pragma unroll
            for (int off = 16; off; off >>= 1)
                v = fmaxf(v, __shfl_xor_sync(0xffffffffu, v, off));
            float e = (lane < O_) ? expf(__fsub_rn(om, v)) : 0.f;
            float s = 0.f;
#pragma unroll
            for (int j = 0; j < O_; ++j)
                s = __fadd_rn(s, __shfl_sync(0xffffffffu, e, j));
            if (t > 10 && lane < O_) accO = __fadd_rn(accO, __fdiv_rn(e, s));
        }
    }

    // outputs: [acc (B,O)] [s1/T (B,H)] [s2/T (B,H)] [A_norm]
    if (lane < O_) out[b * O_ + lane] = accO;
#pragma unroll
    for (int g = 0; g < 4; ++g) {
        int h = g * 32 + lane;
        out[B_ * O_ + b * H_ + h]           = __fdiv_rn(s1c[g], (float)T_);
        out[B_ * O_ + B_ * H_ + b * H_ + h] = __fdiv_rn(s2c[g], (float)T_);
    }
}

// ---------------------------------------------------------------------------
// Kernel 3: A_norm = sum|w_h1h1*mask0| + sum|w_h2h2*mask1|  (fp32)
// ---------------------------------------------------------------------------
__global__ void anorm_kernel(const float* __restrict__ w11, const float* __restrict__ w22,
                             const float* __restrict__ mask, float* __restrict__ out)
{
    __shared__ float red[256];
    float s = 0.f;
    for (int i = threadIdx.x; i < H_ * H_; i += 256)
        s = __fadd_rn(s, __fadd_rn(fabsf(__fmul_rn(w11[i], mask[i])),
                                   fabsf(__fmul_rn(w22[i], mask[H_ * H_ + i]))));
    red[threadIdx.x] = s;
    __syncthreads();
    for (int o = 128; o > 0; o >>= 1) {
        if (threadIdx.x < o) red[threadIdx.x] = __fadd_rn(red[threadIdx.x], red[threadIdx.x + o]);
        __syncthreads();
    }
    if (threadIdx.x == 0) out[B_ * O_ + 2 * B_ * H_] = red[0];
}

// ---------------------------------------------------------------------------
extern "C" void kernel_launch(void* const* d_in, const int* in_sizes, int n_in,
                              void* d_out, int out_size)
{
    const float* x          = (const float*)d_in[0];
    const float* mask       = (const float*)d_in[1];
    const float* w_ih1      = (const float*)d_in[2];
    const float* b_ih1      = (const float*)d_in[3];
    const float* w_h1h1     = (const float*)d_in[4];
    const float* b_h1h1     = (const float*)d_in[5];
    const float* w_h1h2     = (const float*)d_in[6];
    const float* b_h1h2     = (const float*)d_in[7];
    const float* w_h2h2     = (const float*)d_in[8];
    const float* b_h2h2     = (const float*)d_in[9];
    const float* w_h2o      = (const float*)d_in[10];
    const float* b_h2o      = (const float*)d_in[11];
    const float* tau_adp_h1 = (const float*)d_in[12];
    const float* tau_adp_h2 = (const float*)d_in[13];
    const float* tau_m_h1   = (const float*)d_in[14];
    const float* tau_m_h2   = (const float*)d_in[15];
    const float* tau_m_o    = (const float*)d_in[16];
    const float* hid1_mem0  = (const float*)d_in[17];
    const float* hid2_mem0  = (const float*)d_in[18];
    const float* out_mem0   = (const float*)d_in[19];
    float* out = (float*)d_out;

    // opt-in to >48KB dynamic smem for the scan kernel (host-side attribute,
    // not a stream op; graph-capture safe)
    cudaFuncSetAttribute(scan_kernel, cudaFuncAttributeMaxDynamicSharedMemorySize,
                         SCAN_SMEM_BYTES);

    gemm_xin_kernel<<<(B_ * T_) / 128, 256>>>(x, w_ih1, b_ih1);
    scan_kernel<<<B_ / 4, 128, SCAN_SMEM_BYTES>>>(
        mask, w_h1h1, b_h1h1, w_h1h2, b_h1h2, w_h2h2, b_h2h2, w_h2o, b_h2o,
        tau_adp_h1, tau_adp_h2, tau_m_h1, tau_m_h2, tau_m_o,
        hid1_mem0, hid2_mem0, out_mem0, out);
    anorm_kernel<<<1, 256>>>(w_h1h1, w_h2h2, mask, out);
}